// round 1
// baseline (speedup 1.0000x reference)
#include <cuda_runtime.h>
#include <math.h>

#define N_NODES 4096
#define E_TYPES 5
#define W_IN 512
#define W_OUT 128
#define NUM_CLASS 16
#define M_TGT 1024
#define NUM_LAYERS 64
#define H0 (W_IN + E_TYPES * W_OUT)   // 1152
#define NNZ_CAP 2097152

// ---------------- static scratch ----------------
__device__ float g_Xg[N_NODES * W_IN];
__device__ float g_Xw[N_NODES * W_OUT];
__device__ float g_lgcn[E_TYPES * N_NODES * W_OUT];
__device__ float g_watt[E_TYPES];
__device__ float g_beta[E_TYPES];
__device__ float g_Xcat[N_NODES * H0];
__device__ float g_x0[N_NODES * W_OUT];
__device__ float g_xA[N_NODES * W_OUT];
__device__ float g_xB[N_NODES * W_OUT];
__device__ float g_h[N_NODES * W_OUT];
__device__ float g_Z1[N_NODES * W_OUT];
__device__ float g_Z2[N_NODES * W_OUT];
__device__ float g_y[M_TGT * NUM_CLASS];
__device__ int   g_cnt[N_NODES];
__device__ int   g_rowptr[N_NODES + 1];
__device__ float g_dis[N_NODES];
__device__ int   g_col[NNZ_CAP];
__device__ float g_val[NNZ_CAP];

// ---------------- generic tiled fp32 GEMM ----------------
// C[M,N] = act(accScale*(A@B) + resScale*Res + bias)
// act: 0 none, 1 relu, 2 leaky(0.01)
#define BM 64
#define BN 64
#define BK 16
__global__ void gemm_kernel(const float* __restrict__ A, const float* __restrict__ B,
                            float* __restrict__ C, int M, int N, int K,
                            const float* __restrict__ bias, const float* __restrict__ Res,
                            float accScale, float resScale, int act) {
    __shared__ float As[BM][BK];
    __shared__ float Bs[BK][BN];
    int bm = blockIdx.y, bn = blockIdx.x;
    int tid = threadIdx.x;                 // 256
    int tx = tid & 15, ty = tid >> 4;      // 16x16 thread grid, 4x4 micro
    int arow = tid >> 2;                   // 0..63
    int acol = (tid & 3) * 4;              // 0..12
    int brow = tid >> 4;                   // 0..15
    int bcol = (tid & 15) * 4;             // 0..60
    const float* Aptr = A + (long long)(bm * BM + arow) * K + acol;
    const float* Bptr = B + (long long)brow * N + bn * BN + bcol;
    float acc[4][4];
#pragma unroll
    for (int i = 0; i < 4; i++)
#pragma unroll
        for (int j = 0; j < 4; j++) acc[i][j] = 0.f;

    for (int k0 = 0; k0 < K; k0 += BK) {
        float4 av = *(const float4*)(Aptr + k0);
        float4 bv = *(const float4*)(Bptr + (long long)k0 * N);
        *(float4*)&As[arow][acol] = av;
        *(float4*)&Bs[brow][bcol] = bv;
        __syncthreads();
#pragma unroll
        for (int kk = 0; kk < BK; kk++) {
            float a[4], b[4];
#pragma unroll
            for (int i = 0; i < 4; i++) a[i] = As[ty * 4 + i][kk];
#pragma unroll
            for (int j = 0; j < 4; j++) b[j] = Bs[kk][tx * 4 + j];
#pragma unroll
            for (int i = 0; i < 4; i++)
#pragma unroll
                for (int j = 0; j < 4; j++) acc[i][j] += a[i] * b[j];
        }
        __syncthreads();
    }
#pragma unroll
    for (int i = 0; i < 4; i++) {
        int r = bm * BM + ty * 4 + i;
#pragma unroll
        for (int j = 0; j < 4; j++) {
            int c = bn * BN + tx * 4 + j;
            float v = accScale * acc[i][j];
            if (Res)  v += resScale * Res[(long long)r * N + c];
            if (bias) v += bias[c];
            if (act == 1) v = fmaxf(v, 0.f);
            else if (act == 2) v = (v >= 0.f) ? v : 0.01f * v;
            C[(long long)r * N + c] = v;
        }
    }
}

// ---------------- lgcn: sparse column scan of A ----------------
// lgcn[e,n,d] = relu( (Xw[n,d] + sum_{m!=n} A[m,n,e]*Xw[m,d]) / (1 + sum_{m!=n} A[m,n,e]) )
__global__ void lgcn_kernel(const float* __restrict__ A, const float* __restrict__ Xw,
                            float* __restrict__ lgcn) {
    int n = blockIdx.x;
    __shared__ float acc[E_TYPES][W_OUT];
    __shared__ float degs[E_TYPES];
    int tid = threadIdx.x;                 // 256
    for (int i = tid; i < E_TYPES * W_OUT; i += 256) ((float*)acc)[i] = 0.f;
    if (tid < E_TYPES) degs[tid] = 0.f;
    __syncthreads();
    int warp = tid >> 5, lane = tid & 31;
    for (int m0 = warp * 32; m0 < N_NODES; m0 += 8 * 32) {
        int m = m0 + lane;
        const float* ap = A + ((long long)m * N_NODES + n) * E_TYPES;
        float a[E_TYPES];
        bool self = (m == n);
#pragma unroll
        for (int e = 0; e < E_TYPES; e++) a[e] = self ? 0.f : ap[e];
#pragma unroll
        for (int e = 0; e < E_TYPES; e++) {
            unsigned msk = __ballot_sync(0xffffffffu, a[e] != 0.f);
            while (msk) {
                int src = __ffs(msk) - 1;
                msk &= msk - 1;
                float av = __shfl_sync(0xffffffffu, a[e], src);
                int ms = m0 + src;
                const float* xr = Xw + (long long)ms * W_OUT;
#pragma unroll
                for (int p = 0; p < 4; p++) {
                    int d = p * 32 + lane;
                    atomicAdd(&acc[e][d], av * xr[d]);
                }
                if (lane == 0) atomicAdd(&degs[e], av);
            }
        }
    }
    __syncthreads();
    for (int i = tid; i < E_TYPES * W_OUT; i += 256) {
        int e = i / W_OUT, d = i % W_OUT;
        float dinv = 1.f / (degs[e] + 1.f);
        float v = dinv * (acc[e][d] + Xw[(long long)n * W_OUT + d]);
        lgcn[((long long)e * N_NODES + n) * W_OUT + d] = fmaxf(v, 0.f);
    }
}

// ---------------- edge-type attention ----------------
__global__ void att_kernel(const float* __restrict__ lgcn, const float* __restrict__ attw,
                           const float* __restrict__ attb, const float* __restrict__ attq,
                           float* __restrict__ watt) {
    int e = blockIdx.x;
    int tid = threadIdx.x;                 // 1024
    int d = tid & 127, g = tid >> 7;       // 8 n-groups x 128 d
    __shared__ float part[8][W_OUT];
    float s = 0.f;
    const float* base = lgcn + (long long)e * N_NODES * W_OUT;
    int n0 = g * (N_NODES / 8), n1 = n0 + (N_NODES / 8);
    for (int n = n0; n < n1; n++)
        s += attw[n] * base[(long long)n * W_OUT + d];
    part[g][d] = s;
    __syncthreads();
    if (g == 0) {
        float tot = 0.f;
#pragma unroll
        for (int gg = 0; gg < 8; gg++) tot += part[gg][d];
        float tm = tanhf(tot + attb[d]);
        part[0][d] = tm * attq[d];
    }
    __syncthreads();
    for (int o = 64; o; o >>= 1) {
        if (tid < o) part[0][tid] += part[0][tid + o];
        __syncthreads();
    }
    if (tid == 0) watt[e] = part[0][0];
}

__global__ void beta_kernel(const float* __restrict__ watt, float* __restrict__ beta) {
    if (threadIdx.x == 0) {
        float mx = watt[0];
        for (int e = 1; e < E_TYPES; e++) mx = fmaxf(mx, watt[e]);
        float ex[E_TYPES], s = 0.f;
        for (int e = 0; e < E_TYPES; e++) { ex[e] = expf(watt[e] - mx); s += ex[e]; }
        for (int e = 0; e < E_TYPES; e++) beta[e] = (float)E_TYPES * ex[e] / s;
    }
}

// ---------------- X_ = [beta*lgcn (e-major) | X] ----------------
__global__ void xcat_kernel(const float* __restrict__ lgcn, const float* __restrict__ X,
                            const float* __restrict__ beta, float* __restrict__ Xcat) {
    long long idx = (long long)blockIdx.x * 256 + threadIdx.x;
    long long total = (long long)N_NODES * H0;
    if (idx >= total) return;
    int n = (int)(idx / H0), c = (int)(idx % H0);
    float v;
    if (c < E_TYPES * W_OUT) {
        int e = c >> 7, d = c & 127;
        v = beta[e] * lgcn[((long long)e * N_NODES + n) * W_OUT + d];
    } else {
        v = X[(long long)n * W_IN + (c - E_TYPES * W_OUT)];
    }
    Xcat[idx] = v;
}

// ---------------- DGCN adjacency (union pattern) CSR build ----------------
__global__ void rowcnt_kernel(const float* __restrict__ A, int* __restrict__ cnt,
                              float* __restrict__ dis) {
    int i = blockIdx.x;
    int tid = threadIdx.x;                 // 256
    int c = 0;
    for (int j = tid; j < N_NODES; j += 256) {
        const float* ap = A + ((long long)i * N_NODES + j) * E_TYPES;
        bool nz = (j == i);
#pragma unroll
        for (int e = 0; e < E_TYPES; e++) nz |= (ap[e] != 0.f);
        c += nz ? 1 : 0;
    }
    __shared__ int red[256];
    red[tid] = c;
    __syncthreads();
    for (int o = 128; o; o >>= 1) {
        if (tid < o) red[tid] += red[tid + o];
        __syncthreads();
    }
    if (tid == 0) {
        cnt[i] = red[0];
        dis[i] = rsqrtf((float)red[0]);    // row count >= 1 always (self loop)
    }
}

__global__ void scan_kernel(const int* __restrict__ cnt, int* __restrict__ rowptr) {
    __shared__ int warpsum[32];
    int t = threadIdx.x;                   // 1024, 4 elems each
    int v[4], s = 0;
#pragma unroll
    for (int j = 0; j < 4; j++) { v[j] = cnt[t * 4 + j]; s += v[j]; }
    int lane = t & 31, warp = t >> 5;
    int x = s;
#pragma unroll
    for (int o = 1; o < 32; o <<= 1) {
        int y = __shfl_up_sync(0xffffffffu, x, o);
        if (lane >= o) x += y;
    }
    if (lane == 31) warpsum[warp] = x;
    __syncthreads();
    if (warp == 0) {
        int w = warpsum[lane];
#pragma unroll
        for (int o = 1; o < 32; o <<= 1) {
            int y = __shfl_up_sync(0xffffffffu, w, o);
            if (lane >= o) w += y;
        }
        warpsum[lane] = w;
    }
    __syncthreads();
    int excl = x - s + (warp ? warpsum[warp - 1] : 0);
    int run = excl;
    if (t == 0) rowptr[0] = 0;
#pragma unroll
    for (int j = 0; j < 4; j++) { run += v[j]; rowptr[t * 4 + j + 1] = run; }
}

__global__ void fill_csr(const float* __restrict__ A, const int* __restrict__ rowptr,
                         const float* __restrict__ dis, int* __restrict__ col,
                         float* __restrict__ val) {
    int i = blockIdx.x;
    float di = dis[i];
    __shared__ int warpCnt[8];
    __shared__ int blockBase;
    if (threadIdx.x == 0) blockBase = rowptr[i];
    __syncthreads();
    for (int j0 = 0; j0 < N_NODES; j0 += 256) {
        int j = j0 + threadIdx.x;
        const float* ap = A + ((long long)i * N_NODES + j) * E_TYPES;
        bool nz = (j == i);
#pragma unroll
        for (int e = 0; e < E_TYPES; e++) nz |= (ap[e] != 0.f);
        unsigned mask = __ballot_sync(0xffffffffu, nz);
        int warp = threadIdx.x >> 5, lane = threadIdx.x & 31;
        if (lane == 0) warpCnt[warp] = __popc(mask);
        __syncthreads();
        int woff = 0;
        for (int w = 0; w < warp; w++) woff += warpCnt[w];
        int total = 0;
        for (int w = 0; w < 8; w++) total += warpCnt[w];
        if (nz) {
            int pos = blockBase + woff + __popc(mask & ((1u << lane) - 1));
            col[pos] = j;
            val[pos] = di * dis[j];
        }
        __syncthreads();
        if (threadIdx.x == 0) blockBase += total;
        __syncthreads();
    }
}

// ---------------- layer SpMM + initial residual ----------------
// h[i,d] = 0.9 * sum_k val[k]*x[col[k],d] + 0.1 * x0[i,d]
__global__ void spmm_kernel(const int* __restrict__ rowptr, const int* __restrict__ col,
                            const float* __restrict__ val, const float* __restrict__ x,
                            const float* __restrict__ x0, float* __restrict__ h) {
    int i = blockIdx.x;
    int d = threadIdx.x;                   // 128
    int s = rowptr[i], e = rowptr[i + 1];
    __shared__ int cs[128];
    __shared__ float vs[128];
    float acc = 0.f;
    for (int k0 = s; k0 < e; k0 += 128) {
        int cnt = min(128, e - k0);
        if (d < cnt) { cs[d] = col[k0 + d]; vs[d] = val[k0 + d]; }
        __syncthreads();
        for (int t = 0; t < cnt; t++)
            acc += vs[t] * x[(long long)cs[t] * W_OUT + d];
        __syncthreads();
    }
    h[(long long)i * W_OUT + d] = 0.9f * acc + 0.1f * x0[(long long)i * W_OUT + d];
}

// ---------------- gather-head GEMM: y = Z[target_x] @ W2 + b2 ----------------
__global__ void out_kernel(const float* __restrict__ Z, const int* __restrict__ tx,
                           const float* __restrict__ W2, const float* __restrict__ b2,
                           float* __restrict__ y) {
    int r = blockIdx.x;                    // 1024
    int t = threadIdx.x;                   // 128
    __shared__ float z[W_OUT];
    z[t] = Z[(long long)tx[r] * W_OUT + t];
    __syncthreads();
    if (t < NUM_CLASS) {
        float s = b2[t];
        for (int k = 0; k < W_OUT; k++) s += z[k] * W2[k * NUM_CLASS + t];
        y[r * NUM_CLASS + t] = s;
    }
}

__global__ void loss_kernel(const float* __restrict__ y, const int* __restrict__ target,
                            float* __restrict__ out) {
    __shared__ float red[256];
    int tid = threadIdx.x;                 // 256
    float part = 0.f;
    for (int r = tid; r < M_TGT; r += 256) {
        const float* yr = y + r * NUM_CLASS;
        float mx = yr[0];
#pragma unroll
        for (int c = 1; c < NUM_CLASS; c++) mx = fmaxf(mx, yr[c]);
        float se = 0.f;
#pragma unroll
        for (int c = 0; c < NUM_CLASS; c++) se += expf(yr[c] - mx);
        float lse = mx + logf(se);
        part += lse - yr[target[r]];
    }
    red[tid] = part;
    __syncthreads();
    for (int o = 128; o; o >>= 1) {
        if (tid < o) red[tid] += red[tid + o];
        __syncthreads();
    }
    if (tid == 0) out[0] = red[0] / (float)M_TGT;
}

// ---------------- launch ----------------
extern "C" void kernel_launch(void* const* d_in, const int* in_sizes, int n_in,
                              void* d_out, int out_size) {
    const float* A        = (const float*)d_in[0];
    const float* X        = (const float*)d_in[1];
    const int*   target_x = (const int*)d_in[2];
    const int*   target   = (const int*)d_in[3];
    const float* weight   = (const float*)d_in[4];
    const float* attw     = (const float*)d_in[5];
    const float* attb     = (const float*)d_in[6];
    const float* attq     = (const float*)d_in[7];
    const float* Wg       = (const float*)d_in[8];
    const float* bg       = (const float*)d_in[9];
    const float* W0       = (const float*)d_in[10];
    const float* b0       = (const float*)d_in[11];
    const float* Wconvs   = (const float*)d_in[12];
    const float* Wd1      = (const float*)d_in[13];
    const float* bd1      = (const float*)d_in[14];
    const float* W1       = (const float*)d_in[15];
    const float* b1       = (const float*)d_in[16];
    const float* W2       = (const float*)d_in[17];
    const float* b2       = (const float*)d_in[18];

    float *Xg, *Xw, *lgcn, *watt, *beta, *Xcat, *x0, *xA, *xB, *h, *Z1, *Z2, *ybuf, *dis, *val;
    int *cnt, *rowptr, *colp;
    cudaGetSymbolAddress((void**)&Xg, g_Xg);
    cudaGetSymbolAddress((void**)&Xw, g_Xw);
    cudaGetSymbolAddress((void**)&lgcn, g_lgcn);
    cudaGetSymbolAddress((void**)&watt, g_watt);
    cudaGetSymbolAddress((void**)&beta, g_beta);
    cudaGetSymbolAddress((void**)&Xcat, g_Xcat);
    cudaGetSymbolAddress((void**)&x0, g_x0);
    cudaGetSymbolAddress((void**)&xA, g_xA);
    cudaGetSymbolAddress((void**)&xB, g_xB);
    cudaGetSymbolAddress((void**)&h, g_h);
    cudaGetSymbolAddress((void**)&Z1, g_Z1);
    cudaGetSymbolAddress((void**)&Z2, g_Z2);
    cudaGetSymbolAddress((void**)&ybuf, g_y);
    cudaGetSymbolAddress((void**)&cnt, g_cnt);
    cudaGetSymbolAddress((void**)&rowptr, g_rowptr);
    cudaGetSymbolAddress((void**)&dis, g_dis);
    cudaGetSymbolAddress((void**)&colp, g_col);
    cudaGetSymbolAddress((void**)&val, g_val);

    // 1) Xg = leaky(X @ Wg + bg), Xw = leaky(Xg @ weight)
    gemm_kernel<<<dim3(W_IN / BN, N_NODES / BM), 256>>>(X, Wg, Xg, N_NODES, W_IN, W_IN,
                                                        bg, nullptr, 1.f, 0.f, 2);
    gemm_kernel<<<dim3(W_OUT / BN, N_NODES / BM), 256>>>(Xg, weight, Xw, N_NODES, W_OUT, W_IN,
                                                         nullptr, nullptr, 1.f, 0.f, 2);
    // 2) per-edge-type normalized sparse aggregation
    lgcn_kernel<<<N_NODES, 256>>>(A, Xw, lgcn);
    // 3) attention -> beta
    att_kernel<<<E_TYPES, 1024>>>(lgcn, attw, attb, attq, watt);
    beta_kernel<<<1, 32>>>(watt, beta);
    // 4) X_ concat and x0
    {
        long long total = (long long)N_NODES * H0;
        xcat_kernel<<<(unsigned)((total + 255) / 256), 256>>>(lgcn, X, beta, Xcat);
    }
    gemm_kernel<<<dim3(W_OUT / BN, N_NODES / BM), 256>>>(Xcat, W0, x0, N_NODES, W_OUT, H0,
                                                         b0, nullptr, 1.f, 0.f, 1);
    // 5) CSR of normalized union adjacency
    rowcnt_kernel<<<N_NODES, 256>>>(A, cnt, dis);
    scan_kernel<<<1, 1024>>>(cnt, rowptr);
    fill_csr<<<N_NODES, 256>>>(A, rowptr, dis, colp, val);
    // 6) 64 GCNII layers
    const float* xin = x0;
    float* bufs[2] = {xA, xB};
    for (int l = 0; l < NUM_LAYERS; l++) {
        float bl = logf(0.5f / (float)(l + 1) + 1.f);
        spmm_kernel<<<N_NODES, 128>>>(rowptr, colp, val, xin, x0, h);
        float* xout = bufs[l & 1];
        gemm_kernel<<<dim3(W_OUT / BN, N_NODES / BM), 256>>>(h, Wconvs + (long long)l * W_OUT * W_OUT,
                                                             xout, N_NODES, W_OUT, W_OUT,
                                                             nullptr, h, bl, 1.f - bl, 1);
        xin = xout;
    }
    // 7) head
    gemm_kernel<<<dim3(W_OUT / BN, N_NODES / BM), 256>>>(xin, Wd1, Z1, N_NODES, W_OUT, W_OUT,
                                                         bd1, nullptr, 1.f, 0.f, 2);
    gemm_kernel<<<dim3(W_OUT / BN, N_NODES / BM), 256>>>(Z1, W1, Z2, N_NODES, W_OUT, W_OUT,
                                                         b1, nullptr, 1.f, 0.f, 2);
    float* yout;
    bool with_loss;
    if (out_size >= M_TGT * NUM_CLASS + 1) { yout = (float*)d_out + 1; with_loss = true; }
    else if (out_size == M_TGT * NUM_CLASS) { yout = (float*)d_out; with_loss = false; }
    else { yout = ybuf; with_loss = true; }
    out_kernel<<<M_TGT, 128>>>(Z2, target_x, W2, b2, yout);
    if (with_loss) loss_kernel<<<1, 256>>>(yout, target, (float*)d_out);
}